// round 15
// baseline (speedup 1.0000x reference)
#include <cuda_runtime.h>

#define BQ 128
#define SQ 512
#define NQ 10
#define NST 1024
#define TPB 512
#define AMPS 2
#define NWARP 16
#define PI_F 3.14159265358979f

typedef unsigned long long u64;

// scratch (no allocations allowed)
__device__ float g_dta[BQ*SQ*NQ];
__device__ float g_C[BQ*SQ*NQ];

__device__ __forceinline__ float2 cmul(float2 a, float2 b){
  return make_float2(a.x*b.x - a.y*b.y, a.x*b.y + a.y*b.x);
}

// ---- packed f32x2 helpers (Blackwell FFMA2 via PTX); carrier = u64 ----------
__device__ __forceinline__ u64 pk2(float x, float y){
  u64 d; asm("mov.b64 %0,{%1,%2};" : "=l"(d) : "f"(x), "f"(y)); return d;
}
__device__ __forceinline__ float2 up2(u64 d){
  float2 f; asm("mov.b64 {%0,%1},%2;" : "=f"(f.x), "=f"(f.y) : "l"(d)); return f;
}
__device__ __forceinline__ u64 fma2d(u64 a, u64 b, u64 c){
  u64 r; asm("fma.rn.f32x2 %0,%1,%2,%3;" : "=l"(r) : "l"(a), "l"(b), "l"(c)); return r;
}
__device__ __forceinline__ u64 mul2d(u64 a, u64 b){
  u64 r; asm("mul.rn.f32x2 %0,%1,%2;" : "=l"(r) : "l"(a), "l"(b)); return r;
}
__device__ __forceinline__ u64 fixPQ(u64 P, u64 Q){
  float2 p = up2(P), q = up2(Q);
  return pk2(p.x - q.y, p.y + q.x);
}

// verified QSVT gather map
__device__ __forceinline__ int gmap(int a){
  int v = a;
  v ^= (v & 1) << 9;
#pragma unroll
  for (int i = 8; i >= 0; --i) v ^= ((v >> (9-i)) & 1) << (8-i);
  return v;
}

// bit transpose for 512-thread layout: swap 9<->0, 8<->1, 7<->2, 6<->3 (keep 5,4)
__device__ __forceinline__ int bswap2(int x){
  int keep = x & 0x30;
  int b9=(x>>9)&1, b8=(x>>8)&1, b7=(x>>7)&1, b6=(x>>6)&1;
  int b3=(x>>3)&1, b2=(x>>2)&1, b1=(x>>1)&1, b0=x&1;
  return keep | (b0<<9) | (b1<<8) | (b2<<7) | (b3<<6)
              | (b6<<3) | (b7<<2) | (b8<<1) | b9;
}
// inverse of chain gather g(x)=x^(x>>1)
__device__ __forceinline__ int grayinv(int j){
  int x = 0, c = 0;
#pragma unroll
  for (int p = 9; p >= 0; --p){ c ^= (j>>p)&1; x |= c<<p; }
  return x;
}
// 9-bit position swizzle: XOR upper nibble of position into lower nibble
__device__ __forceinline__ int possw(int p){ return p ^ ((p >> 4) & 0xF); }

// ---------------------------------------------------------------------------
__global__ void prep_kernel(const float* __restrict__ angles,
                            const float* __restrict__ W_x,
                            const float* __restrict__ W_dt,
                            const float* __restrict__ b_dt)
{
  int idx = blockIdx.x*blockDim.x + threadIdx.x;
  if (idx >= BQ*SQ) return;
  float a[NQ];
#pragma unroll
  for (int n=0;n<NQ;n++) a[n] = angles[idx*NQ + n];
  float dtr[5];
#pragma unroll
  for (int r=0;r<5;r++){
    float s = 0.f;
#pragma unroll
    for (int n=0;n<NQ;n++) s += a[n]*W_x[r*NQ+n];
    dtr[r]=s;
  }
#pragma unroll
  for (int k=0;k<NQ;k++){
    float s=0.f;
#pragma unroll
    for (int n=0;n<NQ;n++) s += a[n]*W_x[(15+k)*NQ+n];
    g_C[idx*NQ+k]=s;
  }
#pragma unroll
  for (int n=0;n<NQ;n++){
    float s = b_dt[n];
#pragma unroll
    for (int r=0;r<5;r++) s += dtr[r]*W_dt[n*5+r];
    float sp = fmaxf(s, 0.f) + log1pf(expf(-fabsf(s)));
    g_dta[idx*NQ+n] = tanhf(sp)*PI_F;
  }
}

// complex shuffle gate on lane bit q, register coefficients
__device__ __forceinline__ void shflCr(u64* v, const u64* Cq, int q){
  u64 csx=Cq[0], csy=Cq[1], cpx=Cq[2], cpy=Cq[3];
#pragma unroll
  for (int m=0;m<AMPS;m++){
    u64 p = __shfl_xor_sync(0xffffffffu, v[m], 1<<q);
    u64 P = fma2d(cpx, p, mul2d(csx, v[m]));
    u64 Q = fma2d(cpy, p, mul2d(csy, v[m]));
    v[m] = fixPQ(P, Q);
  }
}

// real (RY) shuffle gate on lane bit q
__device__ __forceinline__ void shflRp(u64* v, float c, float s, int q, int lane){
  float sp = ((lane >> q) & 1) ? s : -s;
  u64 c2 = pk2(c, c), sp2 = pk2(sp, sp);
#pragma unroll
  for (int m=0;m<AMPS;m++){
    u64 p = __shfl_xor_sync(0xffffffffu, v[m], 1<<q);
    v[m] = fma2d(sp2, p, mul2d(c2, v[m]));
  }
}

// complex register gate on the m bit (pair 0,1)
__device__ __forceinline__ void regCp(u64* v, const u64* G){
  u64 lo = v[0], hi = v[1];
  u64 P = fma2d(G[2], hi, mul2d(G[0], lo));
  u64 Q = fma2d(G[3], hi, mul2d(G[1], lo));
  v[0] = fixPQ(P, Q);
  P = fma2d(G[6], hi, mul2d(G[4], lo));
  Q = fma2d(G[7], hi, mul2d(G[5], lo));
  v[1] = fixPQ(P, Q);
}

// real register gate on the m bit
__device__ __forceinline__ void regRp(u64* v, float c, float s){
  u64 c2 = pk2(c,c), s2 = pk2(s,s), ns2 = pk2(-s,-s);
  u64 lo = v[0], hi = v[1];
  v[0] = fma2d(ns2, hi, mul2d(c2, lo));
  v[1] = fma2d(c2, hi, mul2d(s2, lo));
}

// ---------------------------------------------------------------------------
// 512 threads, 2 amps/thread, packed (re,im) per u64.
// L0: amp a = 2*tid+m; bit0=m (wire9), bits[5:1]=lane (wires 8..4),
// bits[9:6]=warp bits 0..3 (wires 3..0). L1 = bswap2: warp wires 0..3 land on
// (m, lane0, lane1, lane2). Five transpose exchanges per step (T1,G1,T2,G2,T3),
// chain gathers fused into exchange store addresses; same segment structure as
// the 256-thread R12 winner but 4 warps/SMSP of latency hiding.
// slot(x) = ((x&1)<<9) | possw(x>>1).
// ---------------------------------------------------------------------------
__global__ __launch_bounds__(TPB, 1) void qmamba_main(
    const float* __restrict__ angles,
    const float* __restrict__ poly,
    const float* __restrict__ cparams,
    const float* __restrict__ Dg,
    float* __restrict__ out)
{
  __shared__ u64 bufA[NST], bufB[NST];
  __shared__ float2 Ug[20][4];
  __shared__ u64 Ugp[20][2][4];      // packed shuffle coeffs (staging/shared use)
  __shared__ u64 Urp[4][8];          // packed reg coeffs, gates {0,9,10,19}
  __shared__ float Slo[32], Shi[32], Alo[32], Ahi[32];
  __shared__ float chs[NQ], shs[NQ], whs[NQ], fcs[NQ], fss[NQ];
  __shared__ float pcs[4], Dsh[NQ];
  __shared__ float zred[NWARP][NQ];

  const int tid = threadIdx.x;
  const int lane = tid & 31;
  const int warp = tid >> 5;
  const int b = blockIdx.x;

  // ---- setup ---------------------------------------------------------------
  if (tid < 20) {
    int layer = tid/10, wire = tid%10;
    int k = (layer*NQ + wire)*3;
    float al = cparams[k], be = cparams[k+1], ga = cparams[k+2];
    float sa, ca, sb, cb, sg, cg;
    sincosf(0.5f*al, &sa, &ca);
    sincosf(0.5f*be, &sb, &cb);
    sincosf(0.5f*ga, &sg, &cg);
    float2 m00 = make_float2( cb*ca,  sb*sa);
    float2 m01 = make_float2(-sb*ca, -cb*sa);
    float2 m10 = make_float2( sb*ca, -cb*sa);
    float2 m11 = make_float2( cb*ca, -sb*sa);
    float2 e0 = make_float2(cg, -sg);
    float2 e1 = make_float2(cg,  sg);
    Ug[tid][0] = cmul(e0, m00);
    Ug[tid][1] = cmul(e0, m01);
    Ug[tid][2] = cmul(e1, m10);
    Ug[tid][3] = cmul(e1, m11);
  }
  if (tid < 4) pcs[tid] = poly[tid];
  float pA = 0.f, pC = 0.f;
  if (tid < NQ) {
    Dsh[tid] = Dg[tid];
    int bi = b*SQ*NQ + tid;
    pA = angles[bi]; pC = g_C[bi];
    float dta = g_dta[bi];
    chs[tid] = 1.f; shs[tid] = 0.f;     // h=0 at step 0
    whs[tid] = dta * (0.5f*PI_F);
    float s_, c_;
    __sincosf(0.5f*pA*dta, &s_, &c_);
    fcs[tid] = c_; fss[tid] = s_;
  }
  __syncthreads();

  // static packed shuffle-gate coefficients Ugp[g][bt][c]
  if (tid < 160) {
    int g = tid >> 3;
    int bt = (tid >> 2) & 1;
    int c = tid & 3;
    float2 cs = bt ? Ug[g][3] : Ug[g][0];
    float2 cp = bt ? Ug[g][2] : Ug[g][1];
    float val = (c==0) ? cs.x : (c==1) ? cs.y : (c==2) ? cp.x : cp.y;
    Ugp[g][bt][c] = pk2(val, val);
  }
  // static packed reg-gate coefficients for gates {0,9,10,19}
  if (tid < 32) {
    const int glist[4] = {0,9,10,19};
    int gi = tid >> 3;
    int c = (tid >> 1) & 3;
    int part = tid & 1;
    float2 gv = Ug[glist[gi]][c];
    float val = part ? gv.y : gv.x;
    Urp[gi][2*c+part] = pk2(val, val);
  }

  // per-thread static: QSVT gather powers + exchange index sets
  int rT1[AMPS], rT2[AMPS], rT3[AMPS], rT4[AMPS];
  int dstT[AMPS], dstG[AMPS];
#pragma unroll
  for (int m=0;m<AMPS;m++){
    int a = tid*AMPS + m;
    rT1[m] = gmap(a);
    rT2[m] = gmap(rT1[m]);
    rT3[m] = gmap(rT2[m]);
    rT4[m] = gmap(rT3[m]);
    int xp = bswap2(a);
    dstT[m] = ((xp & 1) << 9) | possw(xp >> 1);
    int xg = grayinv(xp);
    dstG[m] = ((xg & 1) << 9) | possw(xg >> 1);
  }
  const int ldb = possw(tid);          // own-slot swizzled load base
  __syncthreads();

  // ---- hoist 8 hot complex shuffle gates into registers --------------------
  // CC[0..3] = gates 4,5,6,7 (lane bits 4,3,2,1), CC[4..7] = gates 14,15,16,17
  u64 CC[8][4];
  {
    const int gl[8] = {4,5,6,7, 14,15,16,17};
    const int qb[8] = {4,3,2,1, 4,3,2,1};
#pragma unroll
    for (int i=0;i<8;i++){
      int bt = (lane >> qb[i]) & 1;
#pragma unroll
      for (int c=0;c<4;c++) CC[i][c] = Ugp[gl[i]][bt][c];
    }
  }

  u64 v[AMPS];

  // ---- sequential scan -----------------------------------------------------
#pragma unroll 1
  for (int s = 0; s < SQ; ++s) {
    // prefetch next-step per-wire inputs
    float nA=0.f, nD=0.f, nC=0.f;
    if (tid < NQ && s+1 < SQ) {
      int bn = (b*SQ + s + 1)*NQ + tid;
      nA = angles[bn]; nD = g_dta[bn]; nC = g_C[bn];
    }
    // per-step split tables over 5-bit halves
    if (tid < 64) {
      int j = tid & 31;
      bool hi = tid >= 32;
      float sm = 0.f, am = 1.f;
#pragma unroll
      for (int q=0;q<5;q++){
        int w = hi ? (4-q) : (9-q);
        int bit = (j>>q)&1;
        sm += bit ? whs[w] : -whs[w];
        am *= bit ? shs[w] : chs[w];
      }
      if (hi){ Shi[j]=sm; Ahi[j]=am; } else { Slo[j]=sm; Alo[j]=am; }
    }
    __syncthreads();

    // init in registers (L0): product state advanced through entire QSVT block
    {
      float p0=pcs[0], p1=pcs[1], p2=pcs[2], p3=pcs[3];
#pragma unroll
      for (int m=0;m<AMPS;m++){
        float phi = p3*(Shi[rT1[m]>>5] + Slo[rT1[m]&31])
                  + p2*(Shi[rT2[m]>>5] + Slo[rT2[m]&31])
                  + p1*(Shi[rT3[m]>>5] + Slo[rT3[m]&31])
                  + p0*(Shi[rT4[m]>>5] + Slo[rT4[m]&31]);
        float am = Ahi[rT4[m]>>5] * Alo[rT4[m]&31];
        float sp, cp; __sincosf(phi, &sp, &cp);
        v[m] = pk2(am*cp, am*sp);
      }
    }

    // ==== phase A (L0): layer-1 wires 4..8 (shfl), 9 (reg) ====
    shflCr(v, CC[0], 4);               // gate 4 (wire4)
    shflCr(v, CC[1], 3);               // gate 5
    shflCr(v, CC[2], 2);               // gate 6
    shflCr(v, CC[3], 1);               // gate 7
    shflCr(v, Ugp[8][lane&1], 0);      // gate 8 (wire8)
    regCp(v, Urp[1]);                  // gate 9 (wire9, m bit)
    // T1: L0 -> L1
#pragma unroll
    for (int m=0;m<AMPS;m++) bufA[dstT[m]] = v[m];
    __syncthreads();
#pragma unroll
    for (int m=0;m<AMPS;m++) v[m] = bufA[(m<<9) | ldb];
    // ==== phase B (L1): layer-1 wires 0 (reg), 1,2,3 (shfl) ====
    regCp(v, Urp[0]);                  // gate 0
    shflCr(v, Ugp[1][lane&1], 0);      // gate 1 (lane bit0)
    shflCr(v, Ugp[2][(lane>>1)&1], 1); // gate 2
    shflCr(v, Ugp[3][(lane>>2)&1], 2); // gate 3
    // G1: chain gather + back to L0
#pragma unroll
    for (int m=0;m<AMPS;m++) bufB[dstG[m]] = v[m];
    __syncthreads();
#pragma unroll
    for (int m=0;m<AMPS;m++) v[m] = bufB[(m<<9) | ldb];

    // ==== phase C (L0): layer-2 wires 4..8, 9 ====
    shflCr(v, CC[4], 4);               // gate 14
    shflCr(v, CC[5], 3);               // gate 15
    shflCr(v, CC[6], 2);               // gate 16
    shflCr(v, CC[7], 1);               // gate 17
    shflCr(v, Ugp[18][lane&1], 0);     // gate 18
    regCp(v, Urp[3]);                  // gate 19
    // T2: L0 -> L1
#pragma unroll
    for (int m=0;m<AMPS;m++) bufA[dstT[m]] = v[m];
    __syncthreads();
#pragma unroll
    for (int m=0;m<AMPS;m++) v[m] = bufA[(m<<9) | ldb];
    // ==== phase D (L1): layer-2 wires 0,1,2,3 ====
    regCp(v, Urp[2]);                  // gate 10
    shflCr(v, Ugp[11][lane&1], 0);     // gate 11
    shflCr(v, Ugp[12][(lane>>1)&1], 1);// gate 12
    shflCr(v, Ugp[13][(lane>>2)&1], 2);// gate 13
    // G2: chain gather + back to L0
#pragma unroll
    for (int m=0;m<AMPS;m++) bufB[dstG[m]] = v[m];
    __syncthreads();
#pragma unroll
    for (int m=0;m<AMPS;m++) v[m] = bufB[(m<<9) | ldb];

    // ==== phase E (L0): final RY wires 4..8, 9 ====
    shflRp(v, fcs[4], fss[4], 4, lane);
    shflRp(v, fcs[5], fss[5], 3, lane);
    shflRp(v, fcs[6], fss[6], 2, lane);
    shflRp(v, fcs[7], fss[7], 1, lane);
    shflRp(v, fcs[8], fss[8], 0, lane);
    regRp(v, fcs[9], fss[9]);
    // T3: L0 -> L1
#pragma unroll
    for (int m=0;m<AMPS;m++) bufA[dstT[m]] = v[m];
    __syncthreads();
#pragma unroll
    for (int m=0;m<AMPS;m++) v[m] = bufA[(m<<9) | ldb];
    // ==== phase F (L1): final RY wires 0,1,2,3 ====
    regRp(v, fcs[0], fss[0]);
    shflRp(v, fcs[1], fss[1], 0, lane);
    shflRp(v, fcs[2], fss[2], 1, lane);
    shflRp(v, fcs[3], fss[3], 2, lane);

    // ======== measurement (L1 layout) ========
    // L1 index j = 2*tid+m; amp = bswap2(j):
    // wire0<-m; wire1<-l0; wire2<-l1; wire3<-l2; wire4<-l4; wire5<-l3;
    // wire6<-w0; wire7<-w1; wire8<-w2; wire9<-w3.
    float S, Sm;
    {
      float2 f0 = up2(v[0]), f1 = up2(v[1]);
      float pm0 = f0.x*f0.x + f0.y*f0.y;
      float pm1 = f1.x*f1.x + f1.y*f1.y;
      S = pm0 + pm1;
      Sm = pm1;
    }
#pragma unroll
    for (int off=16; off>0; off>>=1)
      Sm += __shfl_xor_sync(0xffffffffu, Sm, off);
    // Walsh-Hadamard on S over 5 lane bits
#pragma unroll
    for (int q=16; q>0; q>>=1){
      float t = __shfl_xor_sync(0xffffffffu, S, q);
      S = ((lane & q) ? (t - S) : (S + t));
    }
    if (lane == 0){
      zred[warp][6] = (warp&1) ? -S : S;
      zred[warp][7] = (warp&2) ? -S : S;
      zred[warp][8] = (warp&4) ? -S : S;
      zred[warp][9] = (warp&8) ? -S : S;
      zred[warp][0] = S - 2.f*Sm;
    } else if (lane == 1)  zred[warp][1] = S;   // sign by l0 -> wire1
    else if (lane == 2)  zred[warp][2] = S;     // l1 -> wire2
    else if (lane == 4)  zred[warp][3] = S;     // l2 -> wire3
    else if (lane == 16) zred[warp][4] = S;     // l4 -> wire4
    else if (lane == 8)  zred[warp][5] = S;     // l3 -> wire5
    __syncthreads();

    if (tid < NQ){
      float hn = 0.f;
#pragma unroll
      for (int w=0; w<NWARP; ++w) hn += zred[w][tid];
      int bi = (b*SQ + s)*NQ + tid;
      out[bi] = pC*hn + Dsh[tid]*pA;
      if (s+1 < SQ){
        float s_, c_;
        __sincosf(0.5f*hn, &s_, &c_);
        chs[tid] = c_; shs[tid] = s_;
        whs[tid] = nD * (0.5f*PI_F);
        __sincosf(0.5f*nA*nD, &s_, &c_);
        fcs[tid] = c_; fss[tid] = s_;
        pA = nA; pC = nC;
      }
    }
    __syncthreads();
  }
}

// ---------------------------------------------------------------------------
extern "C" void kernel_launch(void* const* d_in, const int* in_sizes, int n_in,
                              void* d_out, int out_size)
{
  const float* angles  = (const float*)d_in[0];
  const float* W_x     = (const float*)d_in[1];
  const float* W_dt    = (const float*)d_in[2];
  const float* b_dt    = (const float*)d_in[3];
  const float* poly    = (const float*)d_in[4];
  const float* cparams = (const float*)d_in[5];
  const float* D       = (const float*)d_in[6];
  float* out = (float*)d_out;

  prep_kernel<<<(BQ*SQ + 255)/256, 256>>>(angles, W_x, W_dt, b_dt);
  qmamba_main<<<BQ, TPB>>>(angles, poly, cparams, D, out);
}

// round 16
// speedup vs baseline: 1.2313x; 1.2313x over previous
#include <cuda_runtime.h>

#define BQ 128
#define SQ 512
#define NQ 10
#define NST 1024
#define TPB 256
#define AMPS 4
#define PI_F 3.14159265358979f

typedef unsigned long long u64;

// scratch (no allocations allowed)
__device__ float g_dta[BQ*SQ*NQ];
__device__ float g_C[BQ*SQ*NQ];

__device__ __forceinline__ float2 cmul(float2 a, float2 b){
  return make_float2(a.x*b.x - a.y*b.y, a.x*b.y + a.y*b.x);
}

// ---- packed f32x2 helpers (Blackwell FFMA2 via PTX); carrier = u64 ----------
__device__ __forceinline__ u64 pk2(float x, float y){
  u64 d; asm("mov.b64 %0,{%1,%2};" : "=l"(d) : "f"(x), "f"(y)); return d;
}
__device__ __forceinline__ float2 up2(u64 d){
  float2 f; asm("mov.b64 {%0,%1},%2;" : "=f"(f.x), "=f"(f.y) : "l"(d)); return f;
}
__device__ __forceinline__ u64 fma2d(u64 a, u64 b, u64 c){
  u64 r; asm("fma.rn.f32x2 %0,%1,%2,%3;" : "=l"(r) : "l"(a), "l"(b), "l"(c)); return r;
}
__device__ __forceinline__ u64 mul2d(u64 a, u64 b){
  u64 r; asm("mul.rn.f32x2 %0,%1,%2;" : "=l"(r) : "l"(a), "l"(b)); return r;
}
__device__ __forceinline__ u64 add2d(u64 a, u64 b){
  u64 r; asm("add.rn.f32x2 %0,%1,%2;" : "=l"(r) : "l"(a), "l"(b)); return r;
}
__device__ __forceinline__ u64 fixPQ(u64 P, u64 Q){
  float2 p = up2(P), q = up2(Q);
  return pk2(p.x - q.y, p.y + q.x);
}

// verified QSVT gather map
__device__ __forceinline__ int gmap(int a){
  int v = a;
  v ^= (v & 1) << 9;
#pragma unroll
  for (int i = 8; i >= 0; --i) v ^= ((v >> (9-i)) & 1) << (8-i);
  return v;
}

// bit transpose: swap amp bits 9<->1, 8<->0, 7<->2 (involution)
__device__ __forceinline__ int bswap(int x){
  int keep = x & 0x78;
  int b9=(x>>9)&1, b8=(x>>8)&1, b7=(x>>7)&1;
  int b2=(x>>2)&1, b1=(x>>1)&1, b0=x&1;
  return keep | (b1<<9) | (b0<<8) | (b2<<7) | (b7<<2) | (b9<<1) | b8;
}
// inverse of chain gather g(x)=x^(x>>1)
__device__ __forceinline__ int grayinv(int j){
  int x = 0, c = 0;
#pragma unroll
  for (int p = 9; p >= 0; --p){ c ^= (j>>p)&1; x |= c<<p; }
  return x;
}

// ---------------------------------------------------------------------------
__global__ void prep_kernel(const float* __restrict__ angles,
                            const float* __restrict__ W_x,
                            const float* __restrict__ W_dt,
                            const float* __restrict__ b_dt)
{
  int idx = blockIdx.x*blockDim.x + threadIdx.x;
  if (idx >= BQ*SQ) return;
  float a[NQ];
#pragma unroll
  for (int n=0;n<NQ;n++) a[n] = angles[idx*NQ + n];
  float dtr[5];
#pragma unroll
  for (int r=0;r<5;r++){
    float s = 0.f;
#pragma unroll
    for (int n=0;n<NQ;n++) s += a[n]*W_x[r*NQ+n];
    dtr[r]=s;
  }
#pragma unroll
  for (int k=0;k<NQ;k++){
    float s=0.f;
#pragma unroll
    for (int n=0;n<NQ;n++) s += a[n]*W_x[(15+k)*NQ+n];
    g_C[idx*NQ+k]=s;
  }
#pragma unroll
  for (int n=0;n<NQ;n++){
    float s = b_dt[n];
#pragma unroll
    for (int r=0;r<5;r++) s += dtr[r]*W_dt[n*5+r];
    float sp = fmaxf(s, 0.f) + log1pf(expf(-fabsf(s)));
    g_dta[idx*NQ+n] = tanhf(sp)*PI_F;
  }
}

// complex shuffle gate on lane bit q, register-resident coefficients
__device__ __forceinline__ void shflCr(u64* v, const u64* Cq, int q){
  u64 csx=Cq[0], csy=Cq[1], cpx=Cq[2], cpy=Cq[3];
#pragma unroll
  for (int m=0;m<AMPS;m++){
    u64 p = __shfl_xor_sync(0xffffffffu, v[m], 1<<q);
    u64 P = fma2d(cpx, p, mul2d(csx, v[m]));
    u64 Q = fma2d(cpy, p, mul2d(csy, v[m]));
    v[m] = fixPQ(P, Q);
  }
}

// complex register gate on m-bit bm (shared coefficients)
__device__ __forceinline__ void regCp(u64* v, const u64* G, int bm){
  u64 g0x=G[0],g0y=G[1],g1x=G[2],g1y=G[3],g2x=G[4],g2y=G[5],g3x=G[6],g3y=G[7];
#pragma unroll
  for (int m=0;m<AMPS;m++){
    if (m & bm) continue;
    int mh = m | bm;
    u64 lo = v[m], hi = v[mh];
    u64 P = fma2d(g1x, hi, mul2d(g0x, lo));
    u64 Q = fma2d(g1y, hi, mul2d(g0y, lo));
    v[m]  = fixPQ(P, Q);
    P = fma2d(g3x, hi, mul2d(g2x, lo));
    Q = fma2d(g3y, hi, mul2d(g2y, lo));
    v[mh] = fixPQ(P, Q);
  }
}

// ---------------------------------------------------------------------------
// R13 base (256 threads, 4 amps, transpose exchanges, hoisted coeffs) +
// R16: final-RY section removed analytically. For the pre-RY state:
//   z_j = cos(theta_j) * Z_j - sin(theta_j) * D_j
// with Z_j = sum (-1)^{bit_j} |a|^2, D_j = sum_a Re(a * conj(a XOR bit_j)),
// theta_j = x_j*dt_j.  D for m-wires = register products; lane-wires =
// independent shuffles; warp-wires = bufB reads (state persists there after G2).
// ---------------------------------------------------------------------------
__global__ __launch_bounds__(TPB, 1) void qmamba_main(
    const float* __restrict__ angles,
    const float* __restrict__ poly,
    const float* __restrict__ cparams,
    const float* __restrict__ Dg,
    float* __restrict__ out)
{
  __shared__ u64 bufA[NST], bufB[NST];
  __shared__ float2 Ug[20][4];
  __shared__ u64 Ugp[20][2][4];      // packed shuffle coeffs (staging)
  __shared__ u64 Urp[8][8];          // packed reg coeffs {0,1,8,9,10,11,18,19}
  __shared__ float Slo[32], Shi[32], Alo[32], Ahi[32];
  __shared__ float chs[NQ], shs[NQ], whs[NQ], fc2[NQ], fs2[NQ];
  __shared__ float pcs[4], Dsh[NQ];
  __shared__ float zred[8][NQ];      // Z partials per warp
  __shared__ float zredX[8][NQ];     // D partials per warp

  const int tid = threadIdx.x;
  const int lane = tid & 31;
  const int warp = tid >> 5;
  const int b = blockIdx.x;

  // ---- setup ---------------------------------------------------------------
  if (tid < 20) {
    int layer = tid/10, wire = tid%10;
    int k = (layer*NQ + wire)*3;
    float al = cparams[k], be = cparams[k+1], ga = cparams[k+2];
    float sa, ca, sb, cb, sg, cg;
    sincosf(0.5f*al, &sa, &ca);
    sincosf(0.5f*be, &sb, &cb);
    sincosf(0.5f*ga, &sg, &cg);
    float2 m00 = make_float2( cb*ca,  sb*sa);
    float2 m01 = make_float2(-sb*ca, -cb*sa);
    float2 m10 = make_float2( sb*ca, -cb*sa);
    float2 m11 = make_float2( cb*ca, -sb*sa);
    float2 e0 = make_float2(cg, -sg);
    float2 e1 = make_float2(cg,  sg);
    Ug[tid][0] = cmul(e0, m00);
    Ug[tid][1] = cmul(e0, m01);
    Ug[tid][2] = cmul(e1, m10);
    Ug[tid][3] = cmul(e1, m11);
  }
  if (tid < 4) pcs[tid] = poly[tid];
  float pA = 0.f, pC = 0.f;
  if (tid < NQ) {
    Dsh[tid] = Dg[tid];
    int bi = b*SQ*NQ + tid;
    pA = angles[bi]; pC = g_C[bi];
    float dta = g_dta[bi];
    chs[tid] = 1.f; shs[tid] = 0.f;     // h=0 at step 0
    whs[tid] = dta * (0.5f*PI_F);
    float s_, c_;
    __sincosf(pA*dta, &s_, &c_);        // FULL angle theta = x*dt
    fc2[tid] = c_; fs2[tid] = s_;
  }
  __syncthreads();

  // static packed shuffle-gate coefficients Ugp[g][bt][c] (staging)
  if (tid < 160) {
    int g = tid >> 3;
    int bt = (tid >> 2) & 1;
    int c = tid & 3;
    float2 cs = bt ? Ug[g][3] : Ug[g][0];
    float2 cp = bt ? Ug[g][2] : Ug[g][1];
    float val = (c==0) ? cs.x : (c==1) ? cs.y : (c==2) ? cp.x : cp.y;
    Ugp[g][bt][c] = pk2(val, val);
  }
  // static packed reg-gate coefficients for gates {0,1,8,9,10,11,18,19}
  if (tid < 64) {
    const int glist[8] = {0,1,8,9,10,11,18,19};
    int gi = tid >> 3;
    int c = (tid >> 1) & 3;
    int part = tid & 1;
    float2 gv = Ug[glist[gi]][c];
    float val = part ? gv.y : gv.x;
    Urp[gi][2*c+part] = pk2(val, val);
  }

  // per-thread static: QSVT gather powers + exchange index sets
  int rT1[AMPS], rT2[AMPS], rT3[AMPS], rT4[AMPS];
  int dstT[AMPS], dstG[AMPS];
#pragma unroll
  for (int m=0;m<AMPS;m++){
    int a = tid*AMPS + m;
    rT1[m] = gmap(a);
    rT2[m] = gmap(rT1[m]);
    rT3[m] = gmap(rT2[m]);
    rT4[m] = gmap(rT3[m]);
    int xp = bswap(a);
    int t1 = xp >> 2;
    dstT[m] = ((xp & 3) << 8) | (t1 ^ ((t1 >> 5) & 1));
    int xg = grayinv(xp);
    int tg = xg >> 2;
    dstG[m] = ((xg & 3) << 8) | (tg ^ ((tg >> 5) & 1));
  }
  const int ldb = tid ^ ((tid >> 5) & 1);   // own-slot swizzled load base
  __syncthreads();

  // ---- hoist complex shuffle-gate coefficients into registers --------------
  u64 CC[12][4];
  {
    const int gl[12] = {3,4,5,6,7, 2, 13,14,15,16,17, 12};
    const int qb[12] = {4,3,2,1,0, 0, 4,3,2,1,0, 0};
#pragma unroll
    for (int i=0;i<12;i++){
      int bt = (lane >> qb[i]) & 1;
#pragma unroll
      for (int c=0;c<4;c++) CC[i][c] = Ugp[gl[i]][bt][c];
    }
  }

  u64 v[AMPS];

  // ---- sequential scan -----------------------------------------------------
#pragma unroll 1
  for (int s = 0; s < SQ; ++s) {
    // prefetch next-step per-wire inputs
    float nA=0.f, nD=0.f, nC=0.f;
    if (tid < NQ && s+1 < SQ) {
      int bn = (b*SQ + s + 1)*NQ + tid;
      nA = angles[bn]; nD = g_dta[bn]; nC = g_C[bn];
    }
    // per-step split tables over 5-bit halves
    if (tid < 64) {
      int j = tid & 31;
      bool hi = tid >= 32;
      float sm = 0.f, am = 1.f;
#pragma unroll
      for (int q=0;q<5;q++){
        int w = hi ? (4-q) : (9-q);
        int bit = (j>>q)&1;
        sm += bit ? whs[w] : -whs[w];
        am *= bit ? shs[w] : chs[w];
      }
      if (hi){ Shi[j]=sm; Ahi[j]=am; } else { Slo[j]=sm; Alo[j]=am; }
    }
    __syncthreads();

    // init in registers (L0): product state advanced through entire QSVT block
    {
      float p0=pcs[0], p1=pcs[1], p2=pcs[2], p3=pcs[3];
#pragma unroll
      for (int m=0;m<AMPS;m++){
        float phi = p3*(Shi[rT1[m]>>5] + Slo[rT1[m]&31])
                  + p2*(Shi[rT2[m]>>5] + Slo[rT2[m]&31])
                  + p1*(Shi[rT3[m]>>5] + Slo[rT3[m]&31])
                  + p0*(Shi[rT4[m]>>5] + Slo[rT4[m]&31]);
        float am = Ahi[rT4[m]>>5] * Alo[rT4[m]&31];
        float sp, cp; __sincosf(phi, &sp, &cp);
        v[m] = pk2(am*cp, am*sp);
      }
    }

    // ==== phase A (L0): layer-1 wires 3..7 (shfl), 8,9 (reg) ====
    shflCr(v, CC[0], 4);
    shflCr(v, CC[1], 3);
    shflCr(v, CC[2], 2);
    shflCr(v, CC[3], 1);
    shflCr(v, CC[4], 0);
    regCp(v, Urp[2], 2);   // gate 8
    regCp(v, Urp[3], 1);   // gate 9
    // T1: L0 -> L1
#pragma unroll
    for (int m=0;m<AMPS;m++) bufA[dstT[m]] = v[m];
    __syncthreads();
#pragma unroll
    for (int m=0;m<AMPS;m++) v[m] = bufA[(m<<8) | ldb];
    // ==== phase B (L1): layer-1 wires 0,1 (reg), 2 (lane0) ====
    regCp(v, Urp[0], 2);
    regCp(v, Urp[1], 1);
    shflCr(v, CC[5], 0);
    // G1: chain gather + back to L0
#pragma unroll
    for (int m=0;m<AMPS;m++) bufB[dstG[m]] = v[m];
    __syncthreads();
#pragma unroll
    for (int m=0;m<AMPS;m++) v[m] = bufB[(m<<8) | ldb];

    // ==== phase C (L0): layer-2 wires 3..7, 8,9 ====
    shflCr(v, CC[6], 4);
    shflCr(v, CC[7], 3);
    shflCr(v, CC[8], 2);
    shflCr(v, CC[9], 1);
    shflCr(v, CC[10], 0);
    regCp(v, Urp[6], 2);   // gate 18
    regCp(v, Urp[7], 1);   // gate 19
    // T2: L0 -> L1
#pragma unroll
    for (int m=0;m<AMPS;m++) bufA[dstT[m]] = v[m];
    __syncthreads();
#pragma unroll
    for (int m=0;m<AMPS;m++) v[m] = bufA[(m<<8) | ldb];
    // ==== phase D (L1): layer-2 wires 0,1,2 ====
    regCp(v, Urp[4], 2);
    regCp(v, Urp[5], 1);
    shflCr(v, CC[11], 0);
    // G2: chain gather + back to L0 (bufB retains the pre-measurement state)
#pragma unroll
    for (int m=0;m<AMPS;m++) bufB[dstG[m]] = v[m];
    __syncthreads();
#pragma unroll
    for (int m=0;m<AMPS;m++) v[m] = bufB[(m<<8) | ldb];

    // ======== measurement (L0 layout), final RY folded analytically ========
    // amp bits: [1:0]=m (wires 8,9), [6:2]=lane (wires 3..7), [9:7]=warp (0,1,2)
    float2 f0 = up2(v[0]), f1 = up2(v[1]), f2 = up2(v[2]), f3 = up2(v[3]);
    float pm0 = f0.x*f0.x + f0.y*f0.y;
    float pm1 = f1.x*f1.x + f1.y*f1.y;
    float pm2 = f2.x*f2.x + f2.y*f2.y;
    float pm3 = f3.x*f3.x + f3.y*f3.y;
    float S   = pm0 + pm1 + pm2 + pm3;
    float SbH = pm2 + pm3;   // m&2 -> amp bit1 -> wire 8
    float SbL = pm1 + pm3;   // m&1 -> amp bit0 -> wire 9
    // D for m-bit wires (each pair product x2)
    float D8 = 2.f*((f0.x*f2.x + f0.y*f2.y) + (f1.x*f3.x + f1.y*f3.y));
    float D9 = 2.f*((f0.x*f1.x + f0.y*f1.y) + (f2.x*f3.x + f2.y*f3.y));
    // D for lane-bit wires 3..7 (lane bit q -> wire 7-q); independent shuffles
    float Dl[5];
#pragma unroll
    for (int q=4; q>=0; --q){
      float d = 0.f;
#pragma unroll
      for (int m=0;m<AMPS;m++){
        float2 g = up2(__shfl_xor_sync(0xffffffffu, v[m], 1<<q));
        float2 fm = (m==0)?f0:(m==1)?f1:(m==2)?f2:f3;
        d += fm.x*g.x + fm.y*g.y;
      }
      Dl[7-(q+3)+3 - 3] = d;   // index = 4-q  (wire 7-q stored at [4-q]: q=4->0(w3) .. q=0->4(w7))
    }
    // D for warp-bit wires 0,1,2 via bufB partner reads
    float Dw[3];
    {
      const int msk[3] = {128, 64, 32};   // wire0: amp bit9 -> tid bit7, etc.
#pragma unroll
      for (int w=0; w<3; ++w){
        int pb = ldb ^ msk[w] ^ ((w==2) ? 1 : 0);  // bit5 flip toggles swizzle bit
        float d = 0.f;
#pragma unroll
        for (int m=0;m<AMPS;m++){
          float2 g = up2(bufB[(m<<8) | pb]);
          float2 fm = (m==0)?f0:(m==1)?f1:(m==2)?f2:f3;
          d += fm.x*g.x + fm.y*g.y;
        }
        Dw[w] = d;
      }
    }
    // ---- reduces ----
    // packed butterfly for the 10 D values
    u64 Dp[5];
    Dp[0] = pk2(Dw[0], Dw[1]);
    Dp[1] = pk2(Dw[2], Dl[0]);        // wires 2, 3
    Dp[2] = pk2(Dl[1], Dl[2]);        // wires 4, 5
    Dp[3] = pk2(Dl[3], Dl[4]);        // wires 6, 7
    Dp[4] = pk2(D8, D9);
#pragma unroll
    for (int off=16; off>0; off>>=1){
#pragma unroll
      for (int i=0;i<5;i++)
        Dp[i] = add2d(Dp[i], __shfl_xor_sync(0xffffffffu, Dp[i], off));
    }
    // Z: m-wire reduces + WHT over lane bits
#pragma unroll
    for (int off=16; off>0; off>>=1){
      SbH += __shfl_xor_sync(0xffffffffu, SbH, off);
      SbL += __shfl_xor_sync(0xffffffffu, SbL, off);
    }
#pragma unroll
    for (int q=16; q>0; q>>=1){
      float t = __shfl_xor_sync(0xffffffffu, S, q);
      S = ((lane & q) ? (t - S) : (S + t));
    }
    if (lane == 0){
      zred[warp][0] = (warp&4) ? -S : S;   // amp bit9 = wire 0
      zred[warp][1] = (warp&2) ? -S : S;   // wire 1
      zred[warp][2] = (warp&1) ? -S : S;   // wire 2
      zred[warp][8] = S - 2.f*SbH;         // wire 8
      zred[warp][9] = S - 2.f*SbL;         // wire 9
      float2 d0 = up2(Dp[0]), d1 = up2(Dp[1]), d2 = up2(Dp[2]);
      float2 d3 = up2(Dp[3]), d4 = up2(Dp[4]);
      zredX[warp][0] = d0.x; zredX[warp][1] = d0.y;
      zredX[warp][2] = d1.x; zredX[warp][3] = d1.y;
      zredX[warp][4] = d2.x; zredX[warp][5] = d2.y;
      zredX[warp][6] = d3.x; zredX[warp][7] = d3.y;
      zredX[warp][8] = d4.x; zredX[warp][9] = d4.y;
    } else if (lane == 16) zred[warp][3] = S;   // lane bit4 -> wire 3
    else if (lane == 8)  zred[warp][4] = S;     // wire 4
    else if (lane == 4)  zred[warp][5] = S;     // wire 5
    else if (lane == 2)  zred[warp][6] = S;     // wire 6
    else if (lane == 1)  zred[warp][7] = S;     // wire 7
    __syncthreads();

    // ======== tail: z combine, h update, next-step scalars ========
    if (tid < NQ){
      float Zs = zred[0][tid] + zred[1][tid] + zred[2][tid] + zred[3][tid]
               + zred[4][tid] + zred[5][tid] + zred[6][tid] + zred[7][tid];
      float Ds = zredX[0][tid] + zredX[1][tid] + zredX[2][tid] + zredX[3][tid]
               + zredX[4][tid] + zredX[5][tid] + zredX[6][tid] + zredX[7][tid];
      float hn = fc2[tid]*Zs - fs2[tid]*Ds;
      int bi = (b*SQ + s)*NQ + tid;
      out[bi] = pC*hn + Dsh[tid]*pA;
      if (s+1 < SQ){
        float s_, c_;
        __sincosf(0.5f*hn, &s_, &c_);
        chs[tid] = c_; shs[tid] = s_;
        whs[tid] = nD * (0.5f*PI_F);
        __sincosf(nA*nD, &s_, &c_);      // FULL angle
        fc2[tid] = c_; fs2[tid] = s_;
        pA = nA; pC = nC;
      }
    }
    __syncthreads();
  }
}

// ---------------------------------------------------------------------------
extern "C" void kernel_launch(void* const* d_in, const int* in_sizes, int n_in,
                              void* d_out, int out_size)
{
  const float* angles  = (const float*)d_in[0];
  const float* W_x     = (const float*)d_in[1];
  const float* W_dt    = (const float*)d_in[2];
  const float* b_dt    = (const float*)d_in[3];
  const float* poly    = (const float*)d_in[4];
  const float* cparams = (const float*)d_in[5];
  const float* D       = (const float*)d_in[6];
  float* out = (float*)d_out;

  prep_kernel<<<(BQ*SQ + 255)/256, 256>>>(angles, W_x, W_dt, b_dt);
  qmamba_main<<<BQ, TPB>>>(angles, poly, cparams, D, out);
}

// round 17
// speedup vs baseline: 1.2550x; 1.0192x over previous
#include <cuda_runtime.h>

#define BQ 128
#define SQ 512
#define NQ 10
#define NST 1024
#define TPB 256
#define AMPS 4
#define PI_F 3.14159265358979f

typedef unsigned long long u64;

// scratch (no allocations allowed)
__device__ float g_dta[BQ*SQ*NQ];
__device__ float g_C[BQ*SQ*NQ];

__device__ __forceinline__ float2 cmul(float2 a, float2 b){
  return make_float2(a.x*b.x - a.y*b.y, a.x*b.y + a.y*b.x);
}

// ---- packed f32x2 helpers (Blackwell FFMA2 via PTX); carrier = u64 ----------
__device__ __forceinline__ u64 pk2(float x, float y){
  u64 d; asm("mov.b64 %0,{%1,%2};" : "=l"(d) : "f"(x), "f"(y)); return d;
}
__device__ __forceinline__ float2 up2(u64 d){
  float2 f; asm("mov.b64 {%0,%1},%2;" : "=f"(f.x), "=f"(f.y) : "l"(d)); return f;
}
__device__ __forceinline__ u64 fma2d(u64 a, u64 b, u64 c){
  u64 r; asm("fma.rn.f32x2 %0,%1,%2,%3;" : "=l"(r) : "l"(a), "l"(b), "l"(c)); return r;
}
__device__ __forceinline__ u64 mul2d(u64 a, u64 b){
  u64 r; asm("mul.rn.f32x2 %0,%1,%2;" : "=l"(r) : "l"(a), "l"(b)); return r;
}
__device__ __forceinline__ u64 add2d(u64 a, u64 b){
  u64 r; asm("add.rn.f32x2 %0,%1,%2;" : "=l"(r) : "l"(a), "l"(b)); return r;
}
__device__ __forceinline__ u64 fixPQ(u64 P, u64 Q){
  float2 p = up2(P), q = up2(Q);
  return pk2(p.x - q.y, p.y + q.x);
}

// verified QSVT gather map
__device__ __forceinline__ int gmap(int a){
  int v = a;
  v ^= (v & 1) << 9;
#pragma unroll
  for (int i = 8; i >= 0; --i) v ^= ((v >> (9-i)) & 1) << (8-i);
  return v;
}

// bit transpose: swap amp bits 9<->1, 8<->0, 7<->2 (involution)
__device__ __forceinline__ int bswap(int x){
  int keep = x & 0x78;
  int b9=(x>>9)&1, b8=(x>>8)&1, b7=(x>>7)&1;
  int b2=(x>>2)&1, b1=(x>>1)&1, b0=x&1;
  return keep | (b1<<9) | (b0<<8) | (b2<<7) | (b7<<2) | (b9<<1) | b8;
}
// inverse of chain gather g(x)=x^(x>>1)
__device__ __forceinline__ int grayinv(int j){
  int x = 0, c = 0;
#pragma unroll
  for (int p = 9; p >= 0; --p){ c ^= (j>>p)&1; x |= c<<p; }
  return x;
}

// ---------------------------------------------------------------------------
__global__ void prep_kernel(const float* __restrict__ angles,
                            const float* __restrict__ W_x,
                            const float* __restrict__ W_dt,
                            const float* __restrict__ b_dt)
{
  int idx = blockIdx.x*blockDim.x + threadIdx.x;
  if (idx >= BQ*SQ) return;
  float a[NQ];
#pragma unroll
  for (int n=0;n<NQ;n++) a[n] = angles[idx*NQ + n];
  float dtr[5];
#pragma unroll
  for (int r=0;r<5;r++){
    float s = 0.f;
#pragma unroll
    for (int n=0;n<NQ;n++) s += a[n]*W_x[r*NQ+n];
    dtr[r]=s;
  }
#pragma unroll
  for (int k=0;k<NQ;k++){
    float s=0.f;
#pragma unroll
    for (int n=0;n<NQ;n++) s += a[n]*W_x[(15+k)*NQ+n];
    g_C[idx*NQ+k]=s;
  }
#pragma unroll
  for (int n=0;n<NQ;n++){
    float s = b_dt[n];
#pragma unroll
    for (int r=0;r<5;r++) s += dtr[r]*W_dt[n*5+r];
    float sp = fmaxf(s, 0.f) + log1pf(expf(-fabsf(s)));
    g_dta[idx*NQ+n] = tanhf(sp)*PI_F;
  }
}

// complex shuffle gate on lane bit q, register-resident coefficients
__device__ __forceinline__ void shflCr(u64* v, const u64* Cq, int q){
  u64 csx=Cq[0], csy=Cq[1], cpx=Cq[2], cpy=Cq[3];
#pragma unroll
  for (int m=0;m<AMPS;m++){
    u64 p = __shfl_xor_sync(0xffffffffu, v[m], 1<<q);
    u64 P = fma2d(cpx, p, mul2d(csx, v[m]));
    u64 Q = fma2d(cpy, p, mul2d(csy, v[m]));
    v[m] = fixPQ(P, Q);
  }
}

// real (RY) shuffle gate on lane bit q
__device__ __forceinline__ void shflRp(u64* v, float c, float s, int q, int lane){
  float sp = ((lane >> q) & 1) ? s : -s;
  u64 c2 = pk2(c, c), sp2 = pk2(sp, sp);
#pragma unroll
  for (int m=0;m<AMPS;m++){
    u64 p = __shfl_xor_sync(0xffffffffu, v[m], 1<<q);
    v[m] = fma2d(sp2, p, mul2d(c2, v[m]));
  }
}

// complex register gate on m-bit bm (shared coefficients)
__device__ __forceinline__ void regCp(u64* v, const u64* G, int bm){
  u64 g0x=G[0],g0y=G[1],g1x=G[2],g1y=G[3],g2x=G[4],g2y=G[5],g3x=G[6],g3y=G[7];
#pragma unroll
  for (int m=0;m<AMPS;m++){
    if (m & bm) continue;
    int mh = m | bm;
    u64 lo = v[m], hi = v[mh];
    u64 P = fma2d(g1x, hi, mul2d(g0x, lo));
    u64 Q = fma2d(g1y, hi, mul2d(g0y, lo));
    v[m]  = fixPQ(P, Q);
    P = fma2d(g3x, hi, mul2d(g2x, lo));
    Q = fma2d(g3y, hi, mul2d(g2y, lo));
    v[mh] = fixPQ(P, Q);
  }
}

// real register gate on m-bit bm
__device__ __forceinline__ void regRp(u64* v, float c, float s, int bm){
  u64 c2 = pk2(c,c), s2 = pk2(s,s), ns2 = pk2(-s,-s);
#pragma unroll
  for (int m=0;m<AMPS;m++){
    if (m & bm) continue;
    int mh = m | bm;
    u64 lo = v[m], hi = v[mh];
    v[m]  = fma2d(ns2, hi, mul2d(c2, lo));
    v[mh] = fma2d(c2, hi, mul2d(s2, lo));
  }
}

// ---------------------------------------------------------------------------
// R13 base (256 threads, 4 amps, transpose exchanges, hoisted coeffs) +
// R17: T3 exchange + phase F removed. RY on wires 3..9 applied in registers
// (cheap real gates); wires 0,1,2 folded analytically into measurement:
//   z_j = cos(theta_j)*Z_j - sin(theta_j)*D_j,  D_j = Re<psi|X_j|psi>
// Both invariant under RY on other wires, so D_j is computed from the post-G2
// state in bufB (verified R16 partner indexing) and Z_j from the post-RY(3..9)
// probabilities via the usual warp-signed WHT.
// ---------------------------------------------------------------------------
__global__ __launch_bounds__(TPB, 1) void qmamba_main(
    const float* __restrict__ angles,
    const float* __restrict__ poly,
    const float* __restrict__ cparams,
    const float* __restrict__ Dg,
    float* __restrict__ out)
{
  __shared__ u64 bufA[NST], bufB[NST];
  __shared__ float2 Ug[20][4];
  __shared__ u64 Ugp[20][2][4];      // packed shuffle coeffs (staging)
  __shared__ u64 Urp[8][8];          // packed reg coeffs {0,1,8,9,10,11,18,19}
  __shared__ float Slo[32], Shi[32], Alo[32], Ahi[32];
  __shared__ float chs[NQ], shs[NQ], whs[NQ], fcs[NQ], fss[NQ];
  __shared__ float pcs[4], Dsh[NQ];
  __shared__ float zred[8][NQ];      // Z partials per warp
  __shared__ float zredX[8][3];      // D partials (wires 0,1,2) per warp

  const int tid = threadIdx.x;
  const int lane = tid & 31;
  const int warp = tid >> 5;
  const int b = blockIdx.x;

  // ---- setup ---------------------------------------------------------------
  if (tid < 20) {
    int layer = tid/10, wire = tid%10;
    int k = (layer*NQ + wire)*3;
    float al = cparams[k], be = cparams[k+1], ga = cparams[k+2];
    float sa, ca, sb, cb, sg, cg;
    sincosf(0.5f*al, &sa, &ca);
    sincosf(0.5f*be, &sb, &cb);
    sincosf(0.5f*ga, &sg, &cg);
    float2 m00 = make_float2( cb*ca,  sb*sa);
    float2 m01 = make_float2(-sb*ca, -cb*sa);
    float2 m10 = make_float2( sb*ca, -cb*sa);
    float2 m11 = make_float2( cb*ca, -sb*sa);
    float2 e0 = make_float2(cg, -sg);
    float2 e1 = make_float2(cg,  sg);
    Ug[tid][0] = cmul(e0, m00);
    Ug[tid][1] = cmul(e0, m01);
    Ug[tid][2] = cmul(e1, m10);
    Ug[tid][3] = cmul(e1, m11);
  }
  if (tid < 4) pcs[tid] = poly[tid];
  float pA = 0.f, pC = 0.f;
  if (tid < NQ) {
    Dsh[tid] = Dg[tid];
    int bi = b*SQ*NQ + tid;
    pA = angles[bi]; pC = g_C[bi];
    float dta = g_dta[bi];
    chs[tid] = 1.f; shs[tid] = 0.f;     // h=0 at step 0
    whs[tid] = dta * (0.5f*PI_F);
    float s_, c_;
    __sincosf(0.5f*pA*dta, &s_, &c_);   // half angle
    fcs[tid] = c_; fss[tid] = s_;
  }
  __syncthreads();

  // static packed shuffle-gate coefficients Ugp[g][bt][c] (staging)
  if (tid < 160) {
    int g = tid >> 3;
    int bt = (tid >> 2) & 1;
    int c = tid & 3;
    float2 cs = bt ? Ug[g][3] : Ug[g][0];
    float2 cp = bt ? Ug[g][2] : Ug[g][1];
    float val = (c==0) ? cs.x : (c==1) ? cs.y : (c==2) ? cp.x : cp.y;
    Ugp[g][bt][c] = pk2(val, val);
  }
  // static packed reg-gate coefficients for gates {0,1,8,9,10,11,18,19}
  if (tid < 64) {
    const int glist[8] = {0,1,8,9,10,11,18,19};
    int gi = tid >> 3;
    int c = (tid >> 1) & 3;
    int part = tid & 1;
    float2 gv = Ug[glist[gi]][c];
    float val = part ? gv.y : gv.x;
    Urp[gi][2*c+part] = pk2(val, val);
  }

  // per-thread static: QSVT gather powers + exchange index sets
  int rT1[AMPS], rT2[AMPS], rT3[AMPS], rT4[AMPS];
  int dstT[AMPS], dstG[AMPS];
#pragma unroll
  for (int m=0;m<AMPS;m++){
    int a = tid*AMPS + m;
    rT1[m] = gmap(a);
    rT2[m] = gmap(rT1[m]);
    rT3[m] = gmap(rT2[m]);
    rT4[m] = gmap(rT3[m]);
    int xp = bswap(a);
    int t1 = xp >> 2;
    dstT[m] = ((xp & 3) << 8) | (t1 ^ ((t1 >> 5) & 1));
    int xg = grayinv(xp);
    int tg = xg >> 2;
    dstG[m] = ((xg & 3) << 8) | (tg ^ ((tg >> 5) & 1));
  }
  const int ldb = tid ^ ((tid >> 5) & 1);   // own-slot swizzled load base
  __syncthreads();

  // ---- hoist complex shuffle-gate coefficients into registers --------------
  u64 CC[12][4];
  {
    const int gl[12] = {3,4,5,6,7, 2, 13,14,15,16,17, 12};
    const int qb[12] = {4,3,2,1,0, 0, 4,3,2,1,0, 0};
#pragma unroll
    for (int i=0;i<12;i++){
      int bt = (lane >> qb[i]) & 1;
#pragma unroll
      for (int c=0;c<4;c++) CC[i][c] = Ugp[gl[i]][bt][c];
    }
  }

  u64 v[AMPS];

  // ---- sequential scan -----------------------------------------------------
#pragma unroll 1
  for (int s = 0; s < SQ; ++s) {
    // prefetch next-step per-wire inputs
    float nA=0.f, nD=0.f, nC=0.f;
    if (tid < NQ && s+1 < SQ) {
      int bn = (b*SQ + s + 1)*NQ + tid;
      nA = angles[bn]; nD = g_dta[bn]; nC = g_C[bn];
    }
    // per-step split tables over 5-bit halves
    if (tid < 64) {
      int j = tid & 31;
      bool hi = tid >= 32;
      float sm = 0.f, am = 1.f;
#pragma unroll
      for (int q=0;q<5;q++){
        int w = hi ? (4-q) : (9-q);
        int bit = (j>>q)&1;
        sm += bit ? whs[w] : -whs[w];
        am *= bit ? shs[w] : chs[w];
      }
      if (hi){ Shi[j]=sm; Ahi[j]=am; } else { Slo[j]=sm; Alo[j]=am; }
    }
    __syncthreads();

    // init in registers (L0): product state advanced through entire QSVT block
    {
      float p0=pcs[0], p1=pcs[1], p2=pcs[2], p3=pcs[3];
#pragma unroll
      for (int m=0;m<AMPS;m++){
        float phi = p3*(Shi[rT1[m]>>5] + Slo[rT1[m]&31])
                  + p2*(Shi[rT2[m]>>5] + Slo[rT2[m]&31])
                  + p1*(Shi[rT3[m]>>5] + Slo[rT3[m]&31])
                  + p0*(Shi[rT4[m]>>5] + Slo[rT4[m]&31]);
        float am = Ahi[rT4[m]>>5] * Alo[rT4[m]&31];
        float sp, cp; __sincosf(phi, &sp, &cp);
        v[m] = pk2(am*cp, am*sp);
      }
    }

    // ==== phase A (L0): layer-1 wires 3..7 (shfl), 8,9 (reg) ====
    shflCr(v, CC[0], 4);
    shflCr(v, CC[1], 3);
    shflCr(v, CC[2], 2);
    shflCr(v, CC[3], 1);
    shflCr(v, CC[4], 0);
    regCp(v, Urp[2], 2);   // gate 8
    regCp(v, Urp[3], 1);   // gate 9
    // T1: L0 -> L1
#pragma unroll
    for (int m=0;m<AMPS;m++) bufA[dstT[m]] = v[m];
    __syncthreads();
#pragma unroll
    for (int m=0;m<AMPS;m++) v[m] = bufA[(m<<8) | ldb];
    // ==== phase B (L1): layer-1 wires 0,1 (reg), 2 (lane0) ====
    regCp(v, Urp[0], 2);
    regCp(v, Urp[1], 1);
    shflCr(v, CC[5], 0);
    // G1: chain gather + back to L0
#pragma unroll
    for (int m=0;m<AMPS;m++) bufB[dstG[m]] = v[m];
    __syncthreads();
#pragma unroll
    for (int m=0;m<AMPS;m++) v[m] = bufB[(m<<8) | ldb];

    // ==== phase C (L0): layer-2 wires 3..7, 8,9 ====
    shflCr(v, CC[6], 4);
    shflCr(v, CC[7], 3);
    shflCr(v, CC[8], 2);
    shflCr(v, CC[9], 1);
    shflCr(v, CC[10], 0);
    regCp(v, Urp[6], 2);   // gate 18
    regCp(v, Urp[7], 1);   // gate 19
    // T2: L0 -> L1
#pragma unroll
    for (int m=0;m<AMPS;m++) bufA[dstT[m]] = v[m];
    __syncthreads();
#pragma unroll
    for (int m=0;m<AMPS;m++) v[m] = bufA[(m<<8) | ldb];
    // ==== phase D (L1): layer-2 wires 0,1,2 ====
    regCp(v, Urp[4], 2);
    regCp(v, Urp[5], 1);
    shflCr(v, CC[11], 0);
    // G2: chain gather + back to L0 (bufB retains the pre-RY state)
#pragma unroll
    for (int m=0;m<AMPS;m++) bufB[dstG[m]] = v[m];
    __syncthreads();
#pragma unroll
    for (int m=0;m<AMPS;m++) v[m] = bufB[(m<<8) | ldb];

    // ==== D for warp-bit wires 0,1,2 from pre-RY state (invariant under RY 3..9)
    float Dw[3];
    {
      float2 g0 = up2(v[0]), g1 = up2(v[1]), g2 = up2(v[2]), g3 = up2(v[3]);
      const int msk[3] = {128, 64, 32};   // wire0: amp bit9 -> tid bit7, etc.
#pragma unroll
      for (int w=0; w<3; ++w){
        int pb = ldb ^ msk[w] ^ ((w==2) ? 1 : 0);  // bit5 flip toggles swizzle
        float d = 0.f;
#pragma unroll
        for (int m=0;m<AMPS;m++){
          float2 g = up2(bufB[(m<<8) | pb]);
          float2 fm = (m==0)?g0:(m==1)?g1:(m==2)?g2:g3;
          d += fm.x*g.x + fm.y*g.y;
        }
        Dw[w] = d;
      }
    }

    // ==== final RY on wires 3..9 only (registers; wires 0-2 folded) ====
    shflRp(v, fcs[3], fss[3], 4, lane);
    shflRp(v, fcs[4], fss[4], 3, lane);
    shflRp(v, fcs[5], fss[5], 2, lane);
    shflRp(v, fcs[6], fss[6], 1, lane);
    shflRp(v, fcs[7], fss[7], 0, lane);
    regRp(v, fcs[8], fss[8], 2);
    regRp(v, fcs[9], fss[9], 1);

    // ======== measurement (L0 layout) ========
    // amp bits: [1:0]=m (wires 8,9), [6:2]=lane (wires 3..7), [9:7]=warp (0,1,2)
    float2 f0 = up2(v[0]), f1 = up2(v[1]), f2 = up2(v[2]), f3 = up2(v[3]);
    float pm0 = f0.x*f0.x + f0.y*f0.y;
    float pm1 = f1.x*f1.x + f1.y*f1.y;
    float pm2 = f2.x*f2.x + f2.y*f2.y;
    float pm3 = f3.x*f3.x + f3.y*f3.y;
    float S   = pm0 + pm1 + pm2 + pm3;
    float SbH = pm2 + pm3;   // m&2 -> wire 8
    float SbL = pm1 + pm3;   // m&1 -> wire 9
    // reduces: packed (Dw0,Dw1) + scalar Dw2 + SbH/SbL, then WHT on S
    u64 Dp01 = pk2(Dw[0], Dw[1]);
    float Dw2 = Dw[2];
#pragma unroll
    for (int off=16; off>0; off>>=1){
      Dp01 = add2d(Dp01, __shfl_xor_sync(0xffffffffu, Dp01, off));
      Dw2 += __shfl_xor_sync(0xffffffffu, Dw2, off);
      SbH += __shfl_xor_sync(0xffffffffu, SbH, off);
      SbL += __shfl_xor_sync(0xffffffffu, SbL, off);
    }
#pragma unroll
    for (int q=16; q>0; q>>=1){
      float t = __shfl_xor_sync(0xffffffffu, S, q);
      S = ((lane & q) ? (t - S) : (S + t));
    }
    if (lane == 0){
      zred[warp][0] = (warp&4) ? -S : S;   // amp bit9 = wire 0
      zred[warp][1] = (warp&2) ? -S : S;   // wire 1
      zred[warp][2] = (warp&1) ? -S : S;   // wire 2
      zred[warp][8] = S - 2.f*SbH;         // wire 8
      zred[warp][9] = S - 2.f*SbL;         // wire 9
      float2 d01 = up2(Dp01);
      zredX[warp][0] = d01.x;
      zredX[warp][1] = d01.y;
      zredX[warp][2] = Dw2;
    } else if (lane == 16) zred[warp][3] = S;   // lane bit4 -> wire 3
    else if (lane == 8)  zred[warp][4] = S;     // wire 4
    else if (lane == 4)  zred[warp][5] = S;     // wire 5
    else if (lane == 2)  zred[warp][6] = S;     // wire 6
    else if (lane == 1)  zred[warp][7] = S;     // wire 7
    __syncthreads();

    // ======== tail: z combine, h update, next-step scalars ========
    if (tid < NQ){
      float Zs = zred[0][tid] + zred[1][tid] + zred[2][tid] + zred[3][tid]
               + zred[4][tid] + zred[5][tid] + zred[6][tid] + zred[7][tid];
      float hn;
      if (tid < 3){
        float Ds = zredX[0][tid] + zredX[1][tid] + zredX[2][tid] + zredX[3][tid]
                 + zredX[4][tid] + zredX[5][tid] + zredX[6][tid] + zredX[7][tid];
        float c = fcs[tid], s_h = fss[tid];
        float c2v = c*c - s_h*s_h;          // cos(theta) via double angle
        float s2v = 2.f*c*s_h;              // sin(theta)
        hn = c2v*Zs - s2v*Ds;
      } else {
        hn = Zs;
      }
      int bi = (b*SQ + s)*NQ + tid;
      out[bi] = pC*hn + Dsh[tid]*pA;
      if (s+1 < SQ){
        float s_, c_;
        __sincosf(0.5f*hn, &s_, &c_);
        chs[tid] = c_; shs[tid] = s_;
        whs[tid] = nD * (0.5f*PI_F);
        __sincosf(0.5f*nA*nD, &s_, &c_);    // half angle
        fcs[tid] = c_; fss[tid] = s_;
        pA = nA; pC = nC;
      }
    }
    __syncthreads();
  }
}

// ---------------------------------------------------------------------------
extern "C" void kernel_launch(void* const* d_in, const int* in_sizes, int n_in,
                              void* d_out, int out_size)
{
  const float* angles  = (const float*)d_in[0];
  const float* W_x     = (const float*)d_in[1];
  const float* W_dt    = (const float*)d_in[2];
  const float* b_dt    = (const float*)d_in[3];
  const float* poly    = (const float*)d_in[4];
  const float* cparams = (const float*)d_in[5];
  const float* D       = (const float*)d_in[6];
  float* out = (float*)d_out;

  prep_kernel<<<(BQ*SQ + 255)/256, 256>>>(angles, W_x, W_dt, b_dt);
  qmamba_main<<<BQ, TPB>>>(angles, poly, cparams, D, out);
}